// round 13
// baseline (speedup 1.0000x reference)
#include <cuda_runtime.h>
#include <cuda_bf16.h>
#include <cstdint>

// out[row, i, e] = x[row, i] * W[i, e] + b[i, e]
// rows = 16384, i in [0,200), e in [0,64).
//
// Round-12 probe: strictly LINEAR per-CTA write streams. Each block owns 16
// whole rows (819KB contiguous slab) and writes it front-to-back with no
// address skips: thread t writes chunk slot t of segment 0..4 within each
// row, rows consecutive. W/b for all 5 segments held in registers (~80 regs
// of constants -> 1 CTA/SM; R4 showed occupancy is not the limiter).
// Tests whether DRAM page open/close from the previous configs' 40KB row
// hops accounts for the ~22% DRAM idle.

#define N_NUM    200
#define E4       16                    // float4 per feature
#define COLS     (N_NUM * E4)          // 3200 float4 per row
#define ROW_B    (COLS * 16)           // 51200 bytes per row
#define N_ROWS   16384
#define TPB      320
#define SEGS     5                     // 5 x 320 = 1600 chunks per row
#define RPB      16                    // rows per block
#define NBLOCKS  (N_ROWS / RPB)        // 1024

__device__ __forceinline__ void stg256_cs(void* p, float4 a, float4 b)
{
    asm volatile(
        "st.global.cs.v8.b32 [%0], {%1,%2,%3,%4,%5,%6,%7,%8};"
        :: "l"(p),
           "r"(__float_as_uint(a.x)), "r"(__float_as_uint(a.y)),
           "r"(__float_as_uint(a.z)), "r"(__float_as_uint(a.w)),
           "r"(__float_as_uint(b.x)), "r"(__float_as_uint(b.y)),
           "r"(__float_as_uint(b.z)), "r"(__float_as_uint(b.w))
        : "memory");
}

__global__ __launch_bounds__(TPB, 1)
void numproj_kernel(const float* __restrict__ x,
                    const float4* __restrict__ W4,
                    const float4* __restrict__ B4,
                    float4* __restrict__ out)
{
    const int tid  = threadIdx.x;
    const int row0 = blockIdx.x * RPB;

    // Register-resident W/b for all 5 segments this thread touches per row.
    float4 w0[SEGS], w1[SEGS], b0[SEGS], b1[SEGS];
    int    ii[SEGS];
    #pragma unroll
    for (int s = 0; s < SEGS; ++s) {
        const int c  = s * TPB + tid;     // chunk 0..1599
        const int j0 = 2 * c;
        w0[s] = __ldg(&W4[j0]);
        w1[s] = __ldg(&W4[j0 + 1]);
        b0[s] = __ldg(&B4[j0]);
        b1[s] = __ldg(&B4[j0 + 1]);
        ii[s] = c >> 3;                   // feature index for this segment
    }

    const float* xrow = x + (size_t)row0 * N_NUM;
    char*        op   = (char*)out + (size_t)row0 * ROW_B + (size_t)tid * 32;

    #pragma unroll 1
    for (int r = 0; r < RPB; ++r) {
        // Batch the row's 5 x loads (L2 broadcast hits) for MLP.
        float xv[SEGS];
        #pragma unroll
        for (int s = 0; s < SEGS; ++s)
            xv[s] = __ldg(xrow + ii[s]);

        #pragma unroll
        for (int s = 0; s < SEGS; ++s) {
            float4 o0, o1;
            o0.x = fmaf(xv[s], w0[s].x, b0[s].x);
            o0.y = fmaf(xv[s], w0[s].y, b0[s].y);
            o0.z = fmaf(xv[s], w0[s].z, b0[s].z);
            o0.w = fmaf(xv[s], w0[s].w, b0[s].w);
            o1.x = fmaf(xv[s], w1[s].x, b1[s].x);
            o1.y = fmaf(xv[s], w1[s].y, b1[s].y);
            o1.z = fmaf(xv[s], w1[s].z, b1[s].z);
            o1.w = fmaf(xv[s], w1[s].w, b1[s].w);
            // Segment s sits at byte offset s*10240 within the row: the
            // block's writes advance strictly linearly through its slab.
            stg256_cs(op + (size_t)s * (TPB * 32), o0, o1);
        }
        xrow += N_NUM;
        op   += ROW_B;
    }
}

extern "C" void kernel_launch(void* const* d_in, const int* in_sizes, int n_in,
                              void* d_out, int out_size)
{
    const float*  x  = (const float*) d_in[0];   // [16384, 200] f32
    const float4* W4 = (const float4*)d_in[1];   // [200, 64] f32 -> 3200 float4
    const float4* B4 = (const float4*)d_in[2];
    float4* out = (float4*)d_out;

    numproj_kernel<<<NBLOCKS, TPB>>>(x, W4, B4, out);
}

// round 14
// speedup vs baseline: 1.1807x; 1.1807x over previous
#include <cuda_runtime.h>
#include <cuda_bf16.h>
#include <cstdint>

// out[row, i, e] = x[row, i] * W[i, e] + b[i, e]
// rows = 16384, i in [0,200), e in [0,64).
//
// FINAL — session best (131.2 / 131.2 / 131.4 us across three runs).
// HBM write-roofline kernel at ~6.5 TB/s effective store throughput:
//  - thread-per-32B output chunk; W/b held in registers for all rows
//  - STG.E.256 streaming stores (.cs), fully coalesced, 10KB contiguous
//    bursts per block iteration (320 threads)
//  - x loads are warp-broadcast L2 hits, batched x4 for MLP
//  - regs capped at 32, no smem, no syncs
// Exhaustive sweeps (R2-R12): occupancy 15-93% (saturates ~24-69%), store
// width 128/256b (+8% for 256b), cs/wb policy, 2-25KB bursts + fully-linear
// streams, RPB 16/32, 64-800 thr blocks. All configs above the occupancy
// knee land at 127-130us ncu wall => HBM3e write-bandwidth roofline.

#define N_NUM    200
#define E4       16                   // float4 per feature
#define COLS     (N_NUM * E4)         // 3200 float4 per row
#define CHUNKS   (COLS / 2)           // 1600 32B-chunks per row
#define N_ROWS   16384
#define TPB      320                  // 10 warps -> 10KB contiguous per iter
#define CBLKS    (CHUNKS / TPB)       // 5 column blocks
#define RPB      16                   // rows per block
#define RBLKS    (N_ROWS / RPB)       // 1024 row blocks
#define RUNROLL  4

__device__ __forceinline__ void stg256_cs(void* p, float4 a, float4 b)
{
    asm volatile(
        "st.global.cs.v8.b32 [%0], {%1,%2,%3,%4,%5,%6,%7,%8};"
        :: "l"(p),
           "r"(__float_as_uint(a.x)), "r"(__float_as_uint(a.y)),
           "r"(__float_as_uint(a.z)), "r"(__float_as_uint(a.w)),
           "r"(__float_as_uint(b.x)), "r"(__float_as_uint(b.y)),
           "r"(__float_as_uint(b.z)), "r"(__float_as_uint(b.w))
        : "memory");
}

__global__ __launch_bounds__(TPB, 6)   // keep regs<=32
void numproj_kernel(const float* __restrict__ x,
                    const float4* __restrict__ W4,
                    const float4* __restrict__ B4,
                    float4* __restrict__ out)
{
    const int c    = blockIdx.x * TPB + threadIdx.x;  // 32B chunk 0..1599
    const int j0   = 2 * c;                           // first float4 column
    const int i    = c >> 3;                          // feature 0..199
    const int row0 = blockIdx.y * RPB;

    // Per-column constants held in registers for all rows.
    const float4 w0 = __ldg(&W4[j0]);
    const float4 w1 = __ldg(&W4[j0 + 1]);
    const float4 b0 = __ldg(&B4[j0]);
    const float4 b1 = __ldg(&B4[j0 + 1]);

    const float* xp = x + (size_t)row0 * N_NUM + i;
    char* op = (char*)(out + (size_t)row0 * COLS + j0);
    const size_t row_bytes = (size_t)COLS * sizeof(float4);

    #pragma unroll 1
    for (int r = 0; r < RPB; r += RUNROLL) {
        float xv[RUNROLL];
        #pragma unroll
        for (int u = 0; u < RUNROLL; ++u)
            xv[u] = __ldg(xp + (size_t)u * N_NUM);

        #pragma unroll
        for (int u = 0; u < RUNROLL; ++u) {
            float4 o0, o1;
            o0.x = fmaf(xv[u], w0.x, b0.x);
            o0.y = fmaf(xv[u], w0.y, b0.y);
            o0.z = fmaf(xv[u], w0.z, b0.z);
            o0.w = fmaf(xv[u], w0.w, b0.w);
            o1.x = fmaf(xv[u], w1.x, b1.x);
            o1.y = fmaf(xv[u], w1.y, b1.y);
            o1.z = fmaf(xv[u], w1.z, b1.z);
            o1.w = fmaf(xv[u], w1.w, b1.w);
            stg256_cs(op + (size_t)u * row_bytes, o0, o1);
        }
        xp += (size_t)RUNROLL * N_NUM;
        op += (size_t)RUNROLL * row_bytes;
    }
}

extern "C" void kernel_launch(void* const* d_in, const int* in_sizes, int n_in,
                              void* d_out, int out_size)
{
    const float*  x  = (const float*) d_in[0];   // [16384, 200] f32
    const float4* W4 = (const float4*)d_in[1];   // [200, 64] f32 -> 3200 float4
    const float4* B4 = (const float4*)d_in[2];
    float4* out = (float4*)d_out;

    dim3 grid(CBLKS, RBLKS);   // 5 x 1024 blocks
    numproj_kernel<<<grid, TPB>>>(x, W4, B4, out);
}

// round 15
// speedup vs baseline: 1.2052x; 1.0207x over previous
#include <cuda_runtime.h>
#include <cuda_bf16.h>
#include <cstdint>

// out[row, i, e] = x[row, i] * W[i, e] + b[i, e]
// rows = 16384, i in [0,200), e in [0,64).
//
// FINAL — session best (min 131.2us, reproduced; noise envelope 131-134us).
// HBM write-roofline kernel at ~6.5 TB/s effective store throughput:
//  - thread-per-32B output chunk; W/b held in registers for all rows
//  - STG.E.256 streaming stores (.cs), fully coalesced, 10KB contiguous
//    bursts per block iteration (320 threads)
//  - x loads are warp-broadcast L2 hits, batched x4 for MLP
//  - regs capped at 32, no smem, no syncs
// Sweep conclusions (R2-R13): 256b stores +8%, smem removal +5%; occupancy
// (15-93%), cache policy, burst contiguity (2KB-linear), unroll and block
// shape all flat above the ~24% occupancy knee. 839MB mandated fp32 output
// at ~6.5TB/s = HBM3e write-bandwidth roofline; SM issue <=8%, L2 <=56%.

#define N_NUM    200
#define E4       16                   // float4 per feature
#define COLS     (N_NUM * E4)         // 3200 float4 per row
#define CHUNKS   (COLS / 2)           // 1600 32B-chunks per row
#define N_ROWS   16384
#define TPB      320                  // 10 warps -> 10KB contiguous per iter
#define CBLKS    (CHUNKS / TPB)       // 5 column blocks
#define RPB      16                   // rows per block
#define RBLKS    (N_ROWS / RPB)       // 1024 row blocks
#define RUNROLL  4

__device__ __forceinline__ void stg256_cs(void* p, float4 a, float4 b)
{
    asm volatile(
        "st.global.cs.v8.b32 [%0], {%1,%2,%3,%4,%5,%6,%7,%8};"
        :: "l"(p),
           "r"(__float_as_uint(a.x)), "r"(__float_as_uint(a.y)),
           "r"(__float_as_uint(a.z)), "r"(__float_as_uint(a.w)),
           "r"(__float_as_uint(b.x)), "r"(__float_as_uint(b.y)),
           "r"(__float_as_uint(b.z)), "r"(__float_as_uint(b.w))
        : "memory");
}

__global__ __launch_bounds__(TPB, 6)   // keep regs<=32
void numproj_kernel(const float* __restrict__ x,
                    const float4* __restrict__ W4,
                    const float4* __restrict__ B4,
                    float4* __restrict__ out)
{
    const int c    = blockIdx.x * TPB + threadIdx.x;  // 32B chunk 0..1599
    const int j0   = 2 * c;                           // first float4 column
    const int i    = c >> 3;                          // feature 0..199
    const int row0 = blockIdx.y * RPB;

    // Per-column constants held in registers for all rows.
    const float4 w0 = __ldg(&W4[j0]);
    const float4 w1 = __ldg(&W4[j0 + 1]);
    const float4 b0 = __ldg(&B4[j0]);
    const float4 b1 = __ldg(&B4[j0 + 1]);

    const float* xp = x + (size_t)row0 * N_NUM + i;
    char* op = (char*)(out + (size_t)row0 * COLS + j0);
    const size_t row_bytes = (size_t)COLS * sizeof(float4);

    #pragma unroll 1
    for (int r = 0; r < RPB; r += RUNROLL) {
        float xv[RUNROLL];
        #pragma unroll
        for (int u = 0; u < RUNROLL; ++u)
            xv[u] = __ldg(xp + (size_t)u * N_NUM);

        #pragma unroll
        for (int u = 0; u < RUNROLL; ++u) {
            float4 o0, o1;
            o0.x = fmaf(xv[u], w0.x, b0.x);
            o0.y = fmaf(xv[u], w0.y, b0.y);
            o0.z = fmaf(xv[u], w0.z, b0.z);
            o0.w = fmaf(xv[u], w0.w, b0.w);
            o1.x = fmaf(xv[u], w1.x, b1.x);
            o1.y = fmaf(xv[u], w1.y, b1.y);
            o1.z = fmaf(xv[u], w1.z, b1.z);
            o1.w = fmaf(xv[u], w1.w, b1.w);
            stg256_cs(op + (size_t)u * row_bytes, o0, o1);
        }
        xp += (size_t)RUNROLL * N_NUM;
        op += (size_t)RUNROLL * row_bytes;
    }
}

extern "C" void kernel_launch(void* const* d_in, const int* in_sizes, int n_in,
                              void* d_out, int out_size)
{
    const float*  x  = (const float*) d_in[0];   // [16384, 200] f32
    const float4* W4 = (const float4*)d_in[1];   // [200, 64] f32 -> 3200 float4
    const float4* B4 = (const float4*)d_in[2];
    float4* out = (float4*)d_out;

    dim3 grid(CBLKS, RBLKS);   // 5 x 1024 blocks
    numproj_kernel<<<grid, TPB>>>(x, W4, B4, out);
}